// round 2
// baseline (speedup 1.0000x reference)
#include <cuda_runtime.h>
#include <cuda_bf16.h>

#define THREADS   256
#define TILE_E    64
#define IN_DIM    160
#define HID       128
#define OUTD      64
#define NODE_DIM  64
#define EDGE_DIM  32
// padded shared strides (floats) to kill 2-way bank conflicts on row reads
#define MSTRIDE   164
#define HSTRIDE   132

#define SMEM_FLOATS (IN_DIM*HID + HID*OUTD + HID + OUTD + TILE_E*MSTRIDE + TILE_E*HSTRIDE)
#define SMEM_BYTES  (SMEM_FLOATS * 4)

__global__ __launch_bounds__(THREADS, 1)
void edge_mlp_kernel(const float* __restrict__ x,
                     const float* __restrict__ edge_attr,
                     const float* __restrict__ W1,
                     const float* __restrict__ b1,
                     const float* __restrict__ W2,
                     const float* __restrict__ b2,
                     const void*  __restrict__ edge_index,
                     float* __restrict__ out,
                     int n_edges, int n_nodes)
{
    extern __shared__ float smem[];
    float* w1_s = smem;                         // [160][128]
    float* w2_s = w1_s + IN_DIM * HID;          // [128][64]
    float* b1_s = w2_s + HID * OUTD;            // [128]
    float* b2_s = b1_s + HID;                   // [64]
    float* m_s  = b2_s + OUTD;                  // [64][MSTRIDE]
    float* h_s  = m_s + TILE_E * MSTRIDE;       // [64][HSTRIDE]
    __shared__ int s_is64;

    const int tid = threadIdx.x;

    // ---- detect edge_index dtype (int64 vs int32) from first 32 entries ----
    if (tid == 0) {
        const long long* e64 = (const long long*)edge_index;
        int ok = 1;
        #pragma unroll 1
        for (int i = 0; i < 32; i++) {
            long long v = e64[i];
            if (v < 0 || v >= (long long)n_nodes) ok = 0;
        }
        s_is64 = ok;
    }

    // ---- cooperative weight load (resident for whole block lifetime) ----
    for (int i = tid; i < IN_DIM * HID / 4; i += THREADS)
        ((float4*)w1_s)[i] = ((const float4*)W1)[i];
    for (int i = tid; i < HID * OUTD / 4; i += THREADS)
        ((float4*)w2_s)[i] = ((const float4*)W2)[i];
    if (tid < HID)  b1_s[tid] = b1[tid];
    if (tid < OUTD) b2_s[tid] = b2[tid];
    __syncthreads();

    const int is64 = s_is64;
    const long long* idx64 = (const long long*)edge_index;
    const int*       idx32 = (const int*)edge_index;

    // thread tiling: 16 column-groups x 16 edge-groups
    const int hg = tid & 15;       // column group
    const int eg = tid >> 4;       // edge group
    const int e0 = eg << 2;        // 4 edges per thread
    const int jA = hg << 2;        // GEMM1 cols jA..jA+3  (stride-4: conflict-free LDS.128)
    const int jB = 64 + (hg << 2); // GEMM1 cols jB..jB+3
    const int o0 = hg << 2;        // GEMM2 cols o0..o0+3

    // per-thread bias vectors (loop-invariant)
    const float4 b1A = *(const float4*)(b1_s + jA);
    const float4 b1B = *(const float4*)(b1_s + jB);
    const float4 b2v = *(const float4*)(b2_s + o0);

    const int n_tiles = (n_edges + TILE_E - 1) / TILE_E;
    for (int tile = blockIdx.x; tile < n_tiles; tile += gridDim.x) {
        const int e_base = tile * TILE_E;

        // ---- gather merged = [x[src] | x[tgt] | edge_attr] : 64 x 160 ----
        // 40 float4 per edge, flat-indexed over all 256 threads
        for (int f = tid; f < TILE_E * 40; f += THREADS) {
            const int e  = f / 40;
            const int c  = f - e * 40;
            const int ge = e_base + e;
            float4 v = make_float4(0.f, 0.f, 0.f, 0.f);
            if (ge < n_edges) {
                if (c < 32) {
                    const int which = c >> 4;          // 0 = src, 1 = tgt
                    const int col   = c & 15;
                    const int pos   = ge + which * n_edges;
                    const long long node = is64 ? idx64[pos] : (long long)idx32[pos];
                    v = ((const float4*)(x + node * NODE_DIM))[col];
                } else {
                    v = ((const float4*)(edge_attr + (long long)ge * EDGE_DIM))[c - 32];
                }
            }
            ((float4*)(m_s + e * MSTRIDE))[c] = v;
        }
        __syncthreads();

        // ---- GEMM1: [64 x 160] @ [160 x 128], 4x8 register tile ----
        float acc[4][8];
        #pragma unroll
        for (int i = 0; i < 4; i++)
            #pragma unroll
            for (int j = 0; j < 8; j++)
                acc[i][j] = 0.f;

        const float* m0 = m_s + e0 * MSTRIDE;
        #pragma unroll 4
        for (int k = 0; k < IN_DIM; k++) {
            const float* wr = w1_s + k * HID;
            const float4 wa = *(const float4*)(wr + jA);
            const float4 wb = *(const float4*)(wr + jB);
            float mv[4];
            #pragma unroll
            for (int i = 0; i < 4; i++) mv[i] = m0[i * MSTRIDE + k];
            #pragma unroll
            for (int i = 0; i < 4; i++) {
                acc[i][0] += mv[i] * wa.x;
                acc[i][1] += mv[i] * wa.y;
                acc[i][2] += mv[i] * wa.z;
                acc[i][3] += mv[i] * wa.w;
                acc[i][4] += mv[i] * wb.x;
                acc[i][5] += mv[i] * wb.y;
                acc[i][6] += mv[i] * wb.z;
                acc[i][7] += mv[i] * wb.w;
            }
        }

        // ---- bias + ReLU -> h_s ----
        #pragma unroll
        for (int i = 0; i < 4; i++) {
            float* hr = h_s + (e0 + i) * HSTRIDE;
            float4 a;
            a.x = fmaxf(acc[i][0] + b1A.x, 0.f);
            a.y = fmaxf(acc[i][1] + b1A.y, 0.f);
            a.z = fmaxf(acc[i][2] + b1A.z, 0.f);
            a.w = fmaxf(acc[i][3] + b1A.w, 0.f);
            *(float4*)(hr + jA) = a;
            float4 b;
            b.x = fmaxf(acc[i][4] + b1B.x, 0.f);
            b.y = fmaxf(acc[i][5] + b1B.y, 0.f);
            b.z = fmaxf(acc[i][6] + b1B.z, 0.f);
            b.w = fmaxf(acc[i][7] + b1B.w, 0.f);
            *(float4*)(hr + jB) = b;
        }
        __syncthreads();

        // ---- GEMM2: [64 x 128] @ [128 x 64], 4x4 register tile ----
        float acc2[4][4];
        #pragma unroll
        for (int i = 0; i < 4; i++)
            #pragma unroll
            for (int j = 0; j < 4; j++)
                acc2[i][j] = 0.f;

        const float* h0 = h_s + e0 * HSTRIDE;
        #pragma unroll 4
        for (int k = 0; k < HID; k++) {
            const float4 w = *(const float4*)(w2_s + k * OUTD + o0);
            #pragma unroll
            for (int i = 0; i < 4; i++) {
                const float hv = h0[i * HSTRIDE + k];
                acc2[i][0] += hv * w.x;
                acc2[i][1] += hv * w.y;
                acc2[i][2] += hv * w.z;
                acc2[i][3] += hv * w.w;
            }
        }

        // ---- epilogue: + b2, write out ----
        #pragma unroll
        for (int i = 0; i < 4; i++) {
            const int ge = e_base + e0 + i;
            if (ge < n_edges) {
                float4 r;
                r.x = acc2[i][0] + b2v.x;
                r.y = acc2[i][1] + b2v.y;
                r.z = acc2[i][2] + b2v.z;
                r.w = acc2[i][3] + b2v.w;
                ((float4*)(out + (size_t)ge * OUTD))[hg] = r;
            }
        }
        // no trailing sync needed: next iteration's writes to m_s are fenced by
        // this tile's post-h-store barrier, and h_s writes by the post-load barrier.
    }
}

extern "C" void kernel_launch(void* const* d_in, const int* in_sizes, int n_in,
                              void* d_out, int out_size)
{
    const float* x   = (const float*)d_in[0];
    const float* ea  = (const float*)d_in[1];
    const float* W1  = (const float*)d_in[2];
    const float* b1  = (const float*)d_in[3];
    const float* W2  = (const float*)d_in[4];
    const float* b2  = (const float*)d_in[5];
    const void*  ei  = (const void*)d_in[6];
    float* out = (float*)d_out;

    const int n_nodes = in_sizes[0] / NODE_DIM;
    const int n_edges = in_sizes[1] / EDGE_DIM;
    const int n_tiles = (n_edges + TILE_E - 1) / TILE_E;
    // ~8 tiles per block: small enough tail-imbalance granularity, few enough
    // blocks that weight reload traffic (~112KB/block from L2) is negligible.
    int grid = (n_tiles + 7) / 8;
    if (grid < 1) grid = 1;

    cudaFuncSetAttribute(edge_mlp_kernel,
                         cudaFuncAttributeMaxDynamicSharedMemorySize, SMEM_BYTES);
    edge_mlp_kernel<<<grid, THREADS, SMEM_BYTES>>>(
        x, ea, W1, b1, W2, b2, ei, out, n_edges, n_nodes);
}

// round 5
// speedup vs baseline: 2.7290x; 2.7290x over previous
#include <cuda_runtime.h>
#include <cuda_bf16.h>
#include <cstdint>

#define THREADS  256
#define TILE     128
#define K1       160
#define N1       128
#define K2       128
#define N2       64
#define NODE_DIM 64
#define EDGE_DIM 32

// strides (in bf16 elements) padded for conflict-free ldmatrix
#define AST   168   // A tile + W1T row stride (336 bytes)
#define W2ST  136   // W2T row stride (272 bytes)

// ---- shared memory layout (bytes), all 16B aligned ----
#define OFF_W1H  0
#define OFF_W1L  (OFF_W1H + N1*AST*2)          // 43008
#define OFF_W2H  (OFF_W1L + N1*AST*2)          // 86016
#define OFF_W2L  (OFF_W2H + N2*W2ST*2)         // 103424
#define OFF_AH   (OFF_W2L + N2*W2ST*2)         // 120832
#define OFF_AL   (OFF_AH + TILE*AST*2)         // 163840
#define OFF_B1   (OFF_AL + TILE*AST*2)         // 206848
#define OFF_B2   (OFF_B1 + N1*4)
#define OFF_IS64 (OFF_B2 + N2*4)
#define SMEM_TOTAL (OFF_IS64 + 64)

__device__ __forceinline__ uint32_t s2u(const void* p){
    uint32_t a;
    asm("{ .reg .u64 t; cvta.to.shared.u64 t, %1; cvt.u32.u64 %0, t; }" : "=r"(a) : "l"(p));
    return a;
}
__device__ __forceinline__ void ldsm4(uint32_t& r0, uint32_t& r1, uint32_t& r2, uint32_t& r3,
                                      uint32_t addr){
    asm volatile("ldmatrix.sync.aligned.m8n8.x4.shared.b16 {%0,%1,%2,%3}, [%4];"
                 : "=r"(r0), "=r"(r1), "=r"(r2), "=r"(r3) : "r"(addr));
}
__device__ __forceinline__ void mma16816(float* c,
                                         uint32_t a0, uint32_t a1, uint32_t a2, uint32_t a3,
                                         uint32_t b0, uint32_t b1){
    asm volatile("mma.sync.aligned.m16n8k16.row.col.f32.bf16.bf16.f32 "
                 "{%0,%1,%2,%3}, {%4,%5,%6,%7}, {%8,%9}, {%0,%1,%2,%3};"
                 : "+f"(c[0]), "+f"(c[1]), "+f"(c[2]), "+f"(c[3])
                 : "r"(a0), "r"(a1), "r"(a2), "r"(a3), "r"(b0), "r"(b1));
}
__device__ __forceinline__ uint32_t packbf2(float a, float b){
    __nv_bfloat162 t = __float22bfloat162_rn(make_float2(a, b));
    return *reinterpret_cast<uint32_t*>(&t);
}
__device__ __forceinline__ float2 unpackbf2(uint32_t u){
    __nv_bfloat162 t = *reinterpret_cast<__nv_bfloat162*>(&u);
    return __bfloat1622float2(t);
}
// split a float pair into bf16-hi pair + bf16-lo (residual) pair
__device__ __forceinline__ void split2(float a, float b, uint32_t& hi, uint32_t& lo){
    hi = packbf2(a, b);
    float2 f = unpackbf2(hi);
    lo = packbf2(a - f.x, b - f.y);
}

__global__ __launch_bounds__(THREADS, 1)
void edge_mlp_hmma(const float* __restrict__ x,
                   const float* __restrict__ edge_attr,
                   const float* __restrict__ W1,
                   const float* __restrict__ b1,
                   const float* __restrict__ W2,
                   const float* __restrict__ b2,
                   const void*  __restrict__ edge_index,
                   float* __restrict__ out,
                   int n_edges, int n_nodes)
{
    extern __shared__ __align__(128) char sm[];
    const uint32_t smb = s2u(sm);
    const int tid = threadIdx.x;
    const int wid = tid >> 5;
    const int lid = tid & 31;

    float* b1s = (float*)(sm + OFF_B1);
    float* b2s = (float*)(sm + OFF_B2);

    // ---- dtype detect ----
    if (tid == 0) {
        const long long* e64 = (const long long*)edge_index;
        int ok = 1;
        #pragma unroll 1
        for (int i = 0; i < 32; i++) {
            long long v = e64[i];
            if (v < 0 || v >= (long long)n_nodes) ok = 0;
        }
        *(int*)(sm + OFF_IS64) = ok;
    }

    // ---- weights: transpose to [n][k], bf16 hi/lo split ----
    for (int i = tid; i < K1 * N1; i += THREADS) {
        int k = i >> 7, n = i & 127;
        float w = W1[i];
        __nv_bfloat16 hb = __float2bfloat16(w);
        __nv_bfloat16 lb = __float2bfloat16(w - __bfloat162float(hb));
        int off = n * AST + k;
        *((__nv_bfloat16*)(sm + OFF_W1H) + off) = hb;
        *((__nv_bfloat16*)(sm + OFF_W1L) + off) = lb;
    }
    for (int i = tid; i < K2 * N2; i += THREADS) {
        int k = i >> 6, n = i & 63;
        float w = W2[i];
        __nv_bfloat16 hb = __float2bfloat16(w);
        __nv_bfloat16 lb = __float2bfloat16(w - __bfloat162float(hb));
        int off = n * W2ST + k;
        *((__nv_bfloat16*)(sm + OFF_W2H) + off) = hb;
        *((__nv_bfloat16*)(sm + OFF_W2L) + off) = lb;
    }
    if (tid < N1) b1s[tid] = b1[tid];
    if (tid < N2) b2s[tid] = b2[tid];
    __syncthreads();

    const int is64 = *(int*)(sm + OFF_IS64);
    const long long* idx64 = (const long long*)edge_index;
    const int*       idx32 = (const int*)edge_index;

    // gather: 2 threads per row, 20 float4 each
    const int grow  = tid >> 1;
    const int ghalf = tid & 1;

    // ldmatrix lane addressing
    const int lmrow = lid & 15;                 // A: row within 16
    const int lmk   = (lid >> 4) << 3;          // A: k offset (0 or 8)
    const int bn    = ((lid >> 4) << 3) + (lid & 7); // B: n row within 16 (matrices 0,1 -> n0-7; 2,3 -> n8-15)
    const int bk    = ((lid >> 3) & 1) << 3;    // B: k offset (0 or 8)

    const uint32_t aAH = smb + OFF_AH + (uint32_t)((wid * 16 + lmrow) * AST + lmk) * 2;
    const uint32_t aAL = smb + OFF_AL + (uint32_t)((wid * 16 + lmrow) * AST + lmk) * 2;
    const uint32_t aW1H = smb + OFF_W1H + (uint32_t)(bn * AST + bk) * 2;
    const uint32_t aW1L = smb + OFF_W1L + (uint32_t)(bn * AST + bk) * 2;
    const uint32_t aW2H = smb + OFF_W2H + (uint32_t)(bn * W2ST + bk) * 2;
    const uint32_t aW2L = smb + OFF_W2L + (uint32_t)(bn * W2ST + bk) * 2;

    const int q2 = (lid & 3) << 1;              // fragment col pair base

    const int n_tiles = (n_edges + TILE - 1) / TILE;
    for (int tile = blockIdx.x; tile < n_tiles; tile += gridDim.x) {
        const int e_base = tile * TILE;

        // ================= gather -> A hi/lo bf16 (row-major, stride AST) =================
        {
            const int ge = e_base + grow;
            const float* xs = x;
            const float* xt = x;
            const float* ea = edge_attr;
            bool valid = (ge < n_edges);
            if (valid) {
                long long s, t;
                if (is64) { s = idx64[ge]; t = idx64[ge + n_edges]; }
                else      { s = idx32[ge]; t = idx32[ge + n_edges]; }
                xs = x + s * NODE_DIM;
                xt = x + t * NODE_DIM;
                ea = edge_attr + (long long)ge * EDGE_DIM;
            }
            char* rowH = sm + OFF_AH + grow * AST * 2;
            char* rowL = sm + OFF_AL + grow * AST * 2;
            #pragma unroll
            for (int j = 0; j < 20; j++) {
                const int col = (ghalf * 20 + j) * 4;
                float4 v = make_float4(0.f, 0.f, 0.f, 0.f);
                if (valid) {
                    if (col < 64)       v = *(const float4*)(xs + col);
                    else if (col < 128) v = *(const float4*)(xt + (col - 64));
                    else                v = *(const float4*)(ea + (col - 128));
                }
                uint32_t h01, l01, h23, l23;
                split2(v.x, v.y, h01, l01);
                split2(v.z, v.w, h23, l23);
                *(uint2*)(rowH + col * 2) = make_uint2(h01, h23);
                *(uint2*)(rowL + col * 2) = make_uint2(l01, l23);
            }
        }
        __syncthreads();

        // ================= GEMM1: C1[16 rows x 128 cols] per warp =================
        float C1[16][4];
        #pragma unroll
        for (int i = 0; i < 16; i++)
            #pragma unroll
            for (int j = 0; j < 4; j++) C1[i][j] = 0.f;

        #pragma unroll
        for (int k = 0; k < 10; k++) {
            uint32_t ah0, ah1, ah2, ah3, al0, al1, al2, al3;
            ldsm4(ah0, ah1, ah2, ah3, aAH + k * 32);
            ldsm4(al0, al1, al2, al3, aAL + k * 32);
            #pragma unroll
            for (int nt2 = 0; nt2 < 8; nt2++) {
                uint32_t bh0, bh1, bh2, bh3, bl0, bl1, bl2, bl3;
                const uint32_t boff = (uint32_t)(nt2 * 16 * AST) * 2 + k * 32;
                ldsm4(bh0, bh1, bh2, bh3, aW1H + boff);
                ldsm4(bl0, bl1, bl2, bl3, aW1L + boff);
                mma16816(C1[2*nt2],   ah0, ah1, ah2, ah3, bh0, bh1);
                mma16816(C1[2*nt2],   al0, al1, al2, al3, bh0, bh1);
                mma16816(C1[2*nt2],   ah0, ah1, ah2, ah3, bl0, bl1);
                mma16816(C1[2*nt2+1], ah0, ah1, ah2, ah3, bh2, bh3);
                mma16816(C1[2*nt2+1], al0, al1, al2, al3, bh2, bh3);
                mma16816(C1[2*nt2+1], ah0, ah1, ah2, ah3, bl2, bl3);
            }
        }

        // ================= epilogue1 (regs) + GEMM2 (A from regs) =================
        float C2[8][4];
        #pragma unroll
        for (int i = 0; i < 8; i++)
            #pragma unroll
            for (int j = 0; j < 4; j++) C2[i][j] = 0.f;

        #pragma unroll
        for (int j = 0; j < 8; j++) {
            // bias + relu on C-frags of ntiles 2j, 2j+1  (cols 16j+q2, 16j+8+q2)
            const float2 bA = *(const float2*)(b1s + 16*j + q2);
            const float2 bB = *(const float2*)(b1s + 16*j + 8 + q2);
            float v00 = fmaxf(C1[2*j][0]   + bA.x, 0.f);
            float v01 = fmaxf(C1[2*j][1]   + bA.y, 0.f);
            float v02 = fmaxf(C1[2*j][2]   + bA.x, 0.f);
            float v03 = fmaxf(C1[2*j][3]   + bA.y, 0.f);
            float v10 = fmaxf(C1[2*j+1][0] + bB.x, 0.f);
            float v11 = fmaxf(C1[2*j+1][1] + bB.y, 0.f);
            float v12 = fmaxf(C1[2*j+1][2] + bB.x, 0.f);
            float v13 = fmaxf(C1[2*j+1][3] + bB.y, 0.f);
            // C-frag (pair of ntiles) == A-frag of k-chunk j for GEMM2
            uint32_t ah0, al0, ah1, al1, ah2, al2, ah3, al3;
            split2(v00, v01, ah0, al0);
            split2(v02, v03, ah1, al1);
            split2(v10, v11, ah2, al2);
            split2(v12, v13, ah3, al3);

            #pragma unroll
            for (int nt2 = 0; nt2 < 4; nt2++) {
                uint32_t bh0, bh1, bh2, bh3, bl0, bl1, bl2, bl3;
                const uint32_t boff = (uint32_t)(nt2 * 16 * W2ST) * 2 + j * 32;
                ldsm4(bh0, bh1, bh2, bh3, aW2H + boff);
                ldsm4(bl0, bl1, bl2, bl3, aW2L + boff);
                mma16816(C2[2*nt2],   ah0, ah1, ah2, ah3, bh0, bh1);
                mma16816(C2[2*nt2],   al0, al1, al2, al3, bh0, bh1);
                mma16816(C2[2*nt2],   ah0, ah1, ah2, ah3, bl0, bl1);
                mma16816(C2[2*nt2+1], ah0, ah1, ah2, ah3, bh2, bh3);
                mma16816(C2[2*nt2+1], al0, al1, al2, al3, bh2, bh3);
                mma16816(C2[2*nt2+1], ah0, ah1, ah2, ah3, bl2, bl3);
            }
        }

        // ================= epilogue2: + b2, direct stores =================
        {
            const int r0 = e_base + wid * 16 + (lid >> 2);
            #pragma unroll
            for (int nt = 0; nt < 8; nt++) {
                const int c = nt * 8 + q2;
                const float2 bb = *(const float2*)(b2s + c);
                if (r0 < n_edges) {
                    float2 o0 = make_float2(C2[nt][0] + bb.x, C2[nt][1] + bb.y);
                    *(float2*)(out + (size_t)r0 * N2 + c) = o0;
                }
                if (r0 + 8 < n_edges) {
                    float2 o1 = make_float2(C2[nt][2] + bb.x, C2[nt][3] + bb.y);
                    *(float2*)(out + (size_t)(r0 + 8) * N2 + c) = o1;
                }
            }
        }
        __syncthreads();   // A tile fully consumed before next gather overwrites
    }
}

extern "C" void kernel_launch(void* const* d_in, const int* in_sizes, int n_in,
                              void* d_out, int out_size)
{
    const float* x  = (const float*)d_in[0];
    const float* ea = (const float*)d_in[1];
    const float* W1 = (const float*)d_in[2];
    const float* b1 = (const float*)d_in[3];
    const float* W2 = (const float*)d_in[4];
    const float* b2 = (const float*)d_in[5];
    const void*  ei = (const void*)d_in[6];
    float* out = (float*)d_out;

    const int n_nodes = in_sizes[0] / NODE_DIM;
    const int n_edges = in_sizes[1] / EDGE_DIM;
    const int n_tiles = (n_edges + TILE - 1) / TILE;
    int grid = n_tiles < 148 ? n_tiles : 148;

    cudaFuncSetAttribute(edge_mlp_hmma,
                         cudaFuncAttributeMaxDynamicSharedMemorySize, SMEM_TOTAL);
    edge_mlp_hmma<<<grid, THREADS, SMEM_TOTAL>>>(
        x, ea, W1, b1, W2, b2, ei, out, n_edges, n_nodes);
}